// round 3
// baseline (speedup 1.0000x reference)
#include <cuda_runtime.h>

#define NROWS 8192
#define DDIM  8192
#define KIN   1024
#define NTHREADS 256

typedef unsigned long long ull;

// ---- packed f32x2 helpers (Blackwell sm_103a) ----
__device__ __forceinline__ ull pack2(float lo, float hi) {
    ull r; asm("mov.b64 %0, {%1, %2};" : "=l"(r) : "f"(lo), "f"(hi)); return r;
}
__device__ __forceinline__ void unpack2(ull v, float& lo, float& hi) {
    asm("mov.b64 {%0, %1}, %2;" : "=f"(lo), "=f"(hi) : "l"(v));
}
__device__ __forceinline__ ull f2add(ull a, ull b) {
    ull r; asm("add.rn.f32x2 %0, %1, %2;" : "=l"(r) : "l"(a), "l"(b)); return r;
}
// a - b == fma(b, -1, a)
__device__ __forceinline__ ull f2sub(ull a, ull b) {
    const ull NEG1 = 0xBF800000BF800000ULL;
    ull r; asm("fma.rn.f32x2 %0, %1, %2, %3;" : "=l"(r) : "l"(b), "l"(NEG1), "l"(a)); return r;
}
__device__ __forceinline__ ull f2mul(ull a, ull b) {
    ull r; asm("mul.rn.f32x2 %0, %1, %2;" : "=l"(r) : "l"(a), "l"(b)); return r;
}

// Packed Hadamard over 16 x f32x2 (4 bits; 5th bit folded at pack time)
__device__ __forceinline__ void h16_packed(ull* y) {
#pragma unroll
    for (int m = 8; m >= 1; m >>= 1) {
#pragma unroll
        for (int j = 0; j < 16; j++) {
            if ((j & m) == 0) {
                ull a = y[j], b = y[j | m];
                y[j]     = f2add(a, b);
                y[j | m] = f2sub(a, b);
            }
        }
    }
}

__global__ void __launch_bounds__(NTHREADS, 3) fwht_kernel(
    const float* __restrict__ u, const int* __restrict__ idx, float* __restrict__ out)
{
    __shared__ float sm[DDIM];       // exchange buffer (32 KB)
    __shared__ int   sidx[KIN];      // cached sorted indices (4 KB)
    __shared__ int   slo[NTHREADS + 1];

    const int t   = threadIdx.x;
    const int row = blockIdx.x;
    const int l   = t & 31;   // lane
    const int wp  = t >> 5;   // warp (0..7)

    // ---- cache idx in smem (one int4 per thread) ----
    reinterpret_cast<int4*>(sidx)[t] = reinterpret_cast<const int4*>(idx)[t];
    __syncthreads();

    // ---- thread t owns e-block [32t, 32t+32): find its key range via binary lifting ----
    const int base = t << 5;
    int p = 0;
#pragma unroll
    for (int s = 512; s >= 1; s >>= 1) {
        int np = p + s;
        if (np <= KIN && sidx[np - 1] < base) p = np;
    }
    slo[t] = p;
    if (t == 0) slo[NTHREADS] = KIN;
    __syncthreads();
    const int kend = slo[t + 1];

    // ---- merge-build 32 register values directly from global u (no zero, no scatter) ----
    const float* urow = u + (long)row * KIN;
    float f[32];
    {
        int k = p;
#pragma unroll
        for (int v = 0; v < 32; v++) {
            float acc = 0.f;
            while (k < kend && sidx[k] == base + v) { acc += urow[k]; k++; }
            f[v] = acc;
        }
    }

    ull z[16];

    // ==== Phase A: H32 over e-bits 0..4 (thread owns e = v + 32l + 1024wp) ====
#pragma unroll
    for (int i = 0; i < 16; i++) z[i] = pack2(f[i] + f[i + 16], f[i] - f[i + 16]);
    h16_packed(z);
#pragma unroll
    for (int i = 0; i < 16; i++) unpack2(z[i], f[i], f[i + 16]);

    // ==== X1 write: vectorized STS.128, chunk-swizzled (conflict-free) ====
    // value e = v + 32*l + 1024*wp stored at float addr
    //   l*256 + wp*32 + 4*((v>>2)^(l&7)) + (v&3)
    {
        float4* smv = reinterpret_cast<float4*>(sm);
        const int cbase = l * 64 + wp * 8;
#pragma unroll
        for (int c = 0; c < 8; c++)
            smv[cbase + (c ^ (l & 7))] =
                make_float4(f[4 * c], f[4 * c + 1], f[4 * c + 2], f[4 * c + 3]);
    }
    __syncthreads();

    // ==== Phase B: read e = l + 32r + 1024wp (scalar, conflict-free), H32 over bits 5..9 ====
    {
        const int bb = wp * 32 + ((l >> 2) << 0); // components below
        const int lq = (l >> 2), ls = (l & 3);
#pragma unroll
        for (int r = 0; r < 32; r++)
            f[r] = sm[r * 256 + wp * 32 + ((lq ^ (r & 7)) << 2) + ls];
        (void)bb;
    }
#pragma unroll
    for (int i = 0; i < 16; i++) z[i] = pack2(f[i] + f[i + 16], f[i] - f[i + 16]);
    h16_packed(z);
#pragma unroll
    for (int i = 0; i < 16; i++) unpack2(z[i], f[i], f[i + 16]);
    __syncthreads();   // everyone done reading X1 before X2 overwrites

    // ==== X2 write: scalar STS, bank-swizzled (conflict-free) ====
    // value e = l + 32r + 1024wp stored at float addr r*256 + wp*32 + (l ^ ((r&7)<<2))
#pragma unroll
    for (int r = 0; r < 32; r++)
        sm[r * 256 + wp * 32 + (l ^ ((r & 7) << 2))] = f[r];
    __syncthreads();

    // ==== Phase C: thread owns e = s + 4l + 128wp + 1024w (s=0..3, w=0..7) ====
    // stored addr = mid*256 + w*32 + 4*((l&7)^(mid&7)) + s, mid = (l>>3)|(wp<<2)
    // -> 8x LDS.128 conflict-free; H8 over w; 8x STG.128 coalesced.
    {
        const int mid = (l >> 3) | (wp << 2);
        const float4* smv = reinterpret_cast<const float4*>(sm);
        const int cix = mid * 64 + ((l & 7) ^ (mid & 7));
        ull za[8], zb[8];
#pragma unroll
        for (int w = 0; w < 8; w++) {
            float4 q = smv[cix + w * 8];
            za[w] = pack2(q.x, q.y);
            zb[w] = pack2(q.z, q.w);
        }
#pragma unroll
        for (int m = 4; m >= 1; m >>= 1) {
#pragma unroll
            for (int j = 0; j < 8; j++) {
                if ((j & m) == 0) {
                    ull a = za[j], b = za[j | m];
                    za[j]     = f2add(a, b);
                    za[j | m] = f2sub(a, b);
                    ull c = zb[j], d = zb[j | m];
                    zb[j]     = f2add(c, d);
                    zb[j | m] = f2sub(c, d);
                }
            }
        }
        const float SCALE = 0.011048543456039806f;  // 1/sqrt(8192)
        const ull SC2 = pack2(SCALE, SCALE);
        float4* orow = reinterpret_cast<float4*>(out + (long)row * DDIM);
        const int obase = l + 32 * wp;
#pragma unroll
        for (int w = 0; w < 8; w++) {
            float x0, x1, x2, x3;
            unpack2(f2mul(za[w], SC2), x0, x1);
            unpack2(f2mul(zb[w], SC2), x2, x3);
            orow[obase + 256 * w] = make_float4(x0, x1, x2, x3);
        }
    }
}

extern "C" void kernel_launch(void* const* d_in, const int* in_sizes, int n_in,
                              void* d_out, int out_size)
{
    const float* u   = (const float*)d_in[0];
    const int*   idx = (const int*)d_in[1];
    float*       out = (float*)d_out;
    fwht_kernel<<<NROWS, NTHREADS>>>(u, idx, out);
}

// round 4
// speedup vs baseline: 2.0609x; 2.0609x over previous
#include <cuda_runtime.h>

#define NROWS 8192
#define DDIM  8192
#define KIN   1024
#define NTHREADS 256

typedef unsigned long long ull;

// ---- packed f32x2 helpers (Blackwell sm_103a) ----
__device__ __forceinline__ ull pack2(float lo, float hi) {
    ull r; asm("mov.b64 %0, {%1, %2};" : "=l"(r) : "f"(lo), "f"(hi)); return r;
}
__device__ __forceinline__ void unpack2(ull v, float& lo, float& hi) {
    asm("mov.b64 {%0, %1}, %2;" : "=f"(lo), "=f"(hi) : "l"(v));
}
__device__ __forceinline__ ull f2add(ull a, ull b) {
    ull r; asm("add.rn.f32x2 %0, %1, %2;" : "=l"(r) : "l"(a), "l"(b)); return r;
}
// a - b == fma(b, -1, a)
__device__ __forceinline__ ull f2sub(ull a, ull b) {
    const ull NEG1 = 0xBF800000BF800000ULL;
    ull r; asm("fma.rn.f32x2 %0, %1, %2, %3;" : "=l"(r) : "l"(b), "l"(NEG1), "l"(a)); return r;
}
__device__ __forceinline__ ull f2mul(ull a, ull b) {
    ull r; asm("mul.rn.f32x2 %0, %1, %2;" : "=l"(r) : "l"(a), "l"(b)); return r;
}

// Scatter-buffer swizzle: perturbs only bits >=2, keeps 4-float groups contiguous.
__device__ __forceinline__ int sws(int e) {
    return e ^ (((e >> 5) & 7) << 2);
}

// Packed Hadamard over 16 x f32x2 (4 bits; 5th bit folded at pack time)
__device__ __forceinline__ void h16_packed(ull* y) {
#pragma unroll
    for (int m = 8; m >= 1; m >>= 1) {
#pragma unroll
        for (int j = 0; j < 16; j++) {
            if ((j & m) == 0) {
                ull a = y[j], b = y[j | m];
                y[j]     = f2add(a, b);
                y[j | m] = f2sub(a, b);
            }
        }
    }
}

__global__ void __launch_bounds__(NTHREADS, 3) fwht_kernel(
    const float* __restrict__ u, const int* __restrict__ idx, float* __restrict__ out)
{
    __shared__ float sm[DDIM];   // 32 KB scatter/exchange buffer
    float4* smv = reinterpret_cast<float4*>(sm);

    const int t   = threadIdx.x;
    const int row = blockIdx.x;
    const int l   = t & 31;   // lane
    const int wp  = t >> 5;   // warp (0..7)

    // ---- zero smem (32KB, STS.128, conflict-free) ----
    const float4 z4 = make_float4(0.f, 0.f, 0.f, 0.f);
#pragma unroll
    for (int i = 0; i < DDIM / 4 / NTHREADS; i++) smv[t + NTHREADS * i] = z4;
    __syncthreads();

    // ---- scatter: idx SORTED, duplicates adjacent -> run-leader plain stores ----
    const float* urow = u + (long)row * KIN;
    {
        const int k0 = 4 * t;
        const int4   iv = reinterpret_cast<const int4*>(idx)[t];
        const float4 uv = reinterpret_cast<const float4*>(urow)[t];
        int   id[4] = {iv.x, iv.y, iv.z, iv.w};
        float uu[4] = {uv.x, uv.y, uv.z, uv.w};
        int prev = (t == 0) ? -1 : idx[k0 - 1];
#pragma unroll
        for (int p = 0; p < 4; p++) {
            if (id[p] != prev) {
                float val = uu[p];
                int q = p + 1;
                while (q < 4 && id[q] == id[p]) { val += uu[q]; q++; }
                if (q == 4) {
                    int j = k0 + 4;   // run spills into next quad (rare)
                    while (j < KIN && idx[j] == id[p]) { val += urow[j]; j++; }
                }
                sm[sws(id[p])] = val;
            }
            prev = id[p];
        }
    }
    __syncthreads();

    float f[32];
    ull   z[16];

    // ==== Phase A: thread owns e = 32b + j, b = l + 32wp, j=0..31 (contiguous) ====
    // read: chunk(e=32b+4c+s) = 8b + (c ^ (l&7))  -> 8x LDS.128, conflict-free
    {
        const int cb = ((l + 32 * wp) << 3);
        const int lx = l & 7;
#pragma unroll
        for (int c = 0; c < 8; c++) {
            float4 q = smv[cb + (c ^ lx)];
            f[4 * c] = q.x; f[4 * c + 1] = q.y; f[4 * c + 2] = q.z; f[4 * c + 3] = q.w;
        }
    }
    // H32 over j (e-bits 0..4): fold bit4 into packing, then h16
#pragma unroll
    for (int i = 0; i < 16; i++) z[i] = pack2(f[i] + f[i + 16], f[i] - f[i + 16]);
    h16_packed(z);
#pragma unroll
    for (int i = 0; i < 16; i++) unpack2(z[i], f[i], f[i + 16]);
    __syncthreads();   // all phase-A reads done before X1 overwrites

    // ==== X1 write: value e = v + 32l + 1024wp at chunk l*64 + wp*8 + ((v>>2)^(l&7)) ====
    // 8x STS.128, conflict-free
    {
        const int cbase = l * 64 + wp * 8;
        const int lx = l & 7;
#pragma unroll
        for (int c = 0; c < 8; c++)
            smv[cbase + (c ^ lx)] =
                make_float4(f[4 * c], f[4 * c + 1], f[4 * c + 2], f[4 * c + 3]);
    }
    __syncthreads();

    // ==== Phase B: read e = l + 32r + 1024wp (scalar LDS, conflict-free) ====
    {
        const int lq = l >> 2, ls = l & 3;
#pragma unroll
        for (int r = 0; r < 32; r++)
            f[r] = sm[r * 256 + wp * 32 + ((lq ^ (r & 7)) << 2) + ls];
    }
    // H32 over r (e-bits 5..9)
#pragma unroll
    for (int i = 0; i < 16; i++) z[i] = pack2(f[i] + f[i + 16], f[i] - f[i + 16]);
    h16_packed(z);
#pragma unroll
    for (int i = 0; i < 16; i++) unpack2(z[i], f[i], f[i + 16]);
    __syncthreads();   // all X1 reads done before X2 overwrites

    // ==== X2 write: value e = l + 32r + 1024wp at r*256 + wp*32 + (l ^ ((r&7)<<2)) ====
    // 32 scalar STS, conflict-free
#pragma unroll
    for (int r = 0; r < 32; r++)
        sm[r * 256 + wp * 32 + (l ^ ((r & 7) << 2))] = f[r];
    __syncthreads();

    // ==== Phase C: thread owns e = s + 4l + 128wp + 1024w (s=0..3, w=0..7) ====
    // read chunk = mid*64 + 8w + ((l&7)^(mid&7)), mid = (l>>3)|(wp<<2)
    // 8x LDS.128 conflict-free; H8 over w; 8x STG.128 coalesced.
    {
        const int mid = (l >> 3) | (wp << 2);
        const int cix = mid * 64 + ((l & 7) ^ (mid & 7));
        ull za[8], zb[8];
#pragma unroll
        for (int w = 0; w < 8; w++) {
            float4 q = smv[cix + w * 8];
            za[w] = pack2(q.x, q.y);
            zb[w] = pack2(q.z, q.w);
        }
#pragma unroll
        for (int m = 4; m >= 1; m >>= 1) {
#pragma unroll
            for (int j = 0; j < 8; j++) {
                if ((j & m) == 0) {
                    ull a = za[j], b = za[j | m];
                    za[j]     = f2add(a, b);
                    za[j | m] = f2sub(a, b);
                    ull c = zb[j], d = zb[j | m];
                    zb[j]     = f2add(c, d);
                    zb[j | m] = f2sub(c, d);
                }
            }
        }
        const float SCALE = 0.011048543456039806f;  // 1/sqrt(8192)
        const ull SC2 = pack2(SCALE, SCALE);
        float4* orow = reinterpret_cast<float4*>(out + (long)row * DDIM);
        const int obase = l + 32 * wp;
#pragma unroll
        for (int w = 0; w < 8; w++) {
            float x0, x1, x2, x3;
            unpack2(f2mul(za[w], SC2), x0, x1);
            unpack2(f2mul(zb[w], SC2), x2, x3);
            orow[obase + 256 * w] = make_float4(x0, x1, x2, x3);
        }
    }
}

extern "C" void kernel_launch(void* const* d_in, const int* in_sizes, int n_in,
                              void* d_out, int out_size)
{
    const float* u   = (const float*)d_in[0];
    const int*   idx = (const int*)d_in[1];
    float*       out = (float*)d_out;
    fwht_kernel<<<NROWS, NTHREADS>>>(u, idx, out);
}

// round 5
// speedup vs baseline: 2.0617x; 1.0004x over previous
#include <cuda_runtime.h>

#define NROWS 8192
#define DDIM  8192
#define KIN   1024
#define NTHREADS 256

typedef unsigned long long ull;

// ---- packed f32x2 helpers (Blackwell sm_103a) ----
__device__ __forceinline__ ull pack2(float lo, float hi) {
    ull r; asm("mov.b64 %0, {%1, %2};" : "=l"(r) : "f"(lo), "f"(hi)); return r;
}
__device__ __forceinline__ void unpack2(ull v, float& lo, float& hi) {
    asm("mov.b64 {%0, %1}, %2;" : "=f"(lo), "=f"(hi) : "l"(v));
}
__device__ __forceinline__ ull f2add(ull a, ull b) {
    ull r; asm("add.rn.f32x2 %0, %1, %2;" : "=l"(r) : "l"(a), "l"(b)); return r;
}
// a - b == fma(b, -1, a)
__device__ __forceinline__ ull f2sub(ull a, ull b) {
    const ull NEG1 = 0xBF800000BF800000ULL;
    ull r; asm("fma.rn.f32x2 %0, %1, %2, %3;" : "=l"(r) : "l"(b), "l"(NEG1), "l"(a)); return r;
}
__device__ __forceinline__ ull f2mul(ull a, ull b) {
    ull r; asm("mul.rn.f32x2 %0, %1, %2;" : "=l"(r) : "l"(a), "l"(b)); return r;
}

// Single storage layout used by ALL phases (in-place updates):
// slot(e) = e ^ (((e>>5)&7)<<2)   -- perturbs bits 2..4 only.
__device__ __forceinline__ int sws(int e) {
    return e ^ (((e >> 5) & 7) << 2);
}

// Packed Hadamard over 16 x f32x2 (4 bits; 5th bit folded at pack time)
__device__ __forceinline__ void h16_packed(ull* y) {
#pragma unroll
    for (int m = 8; m >= 1; m >>= 1) {
#pragma unroll
        for (int j = 0; j < 16; j++) {
            if ((j & m) == 0) {
                ull a = y[j], b = y[j | m];
                y[j]     = f2add(a, b);
                y[j | m] = f2sub(a, b);
            }
        }
    }
}

__global__ void __launch_bounds__(NTHREADS, 3) fwht_kernel(
    const float* __restrict__ u, const int* __restrict__ idx, float* __restrict__ out)
{
    __shared__ float sm[DDIM];   // 32 KB, single in-place buffer
    float4* smv = reinterpret_cast<float4*>(sm);

    const int t   = threadIdx.x;
    const int row = blockIdx.x;
    const int l   = t & 31;   // lane
    const int wp  = t >> 5;   // warp (0..7)

    // ---- early global loads (overlap DRAM latency with the zero pass) ----
    const float* urow = u + (long)row * KIN;
    const int4   iv = reinterpret_cast<const int4*>(idx)[t];
    const float4 uv = reinterpret_cast<const float4*>(urow)[t];
    const int    k0 = 4 * t;
    int prev = (t == 0) ? -1 : idx[k0 - 1];

    // ---- zero smem (32KB, STS.128, conflict-free) ----
    const float4 z4 = make_float4(0.f, 0.f, 0.f, 0.f);
#pragma unroll
    for (int i = 0; i < DDIM / 4 / NTHREADS; i++) smv[t + NTHREADS * i] = z4;
    __syncthreads();

    // ---- scatter: idx SORTED, duplicates adjacent -> run-leader plain stores ----
    {
        int   id[4] = {iv.x, iv.y, iv.z, iv.w};
        float uu[4] = {uv.x, uv.y, uv.z, uv.w};
#pragma unroll
        for (int p = 0; p < 4; p++) {
            if (id[p] != prev) {
                float val = uu[p];
                int q = p + 1;
                while (q < 4 && id[q] == id[p]) { val += uu[q]; q++; }
                if (q == 4) {
                    int j = k0 + 4;   // run spills into next quad (rare)
                    while (j < KIN && idx[j] == id[p]) { val += urow[j]; j++; }
                }
                sm[sws(id[p])] = val;
            }
            prev = id[p];
        }
    }
    __syncthreads();

    float f[32];
    ull   z[16];

    // ==== Phase A: thread owns e = j + 32l + 1024wp (j=0..31 contiguous) ====
    // chunk(e-quad c) = (l+32wp)*8 + (c ^ (l&7)) -> 8x LDS.128, conflict-free
    const int cb = ((l + 32 * wp) << 3);
    const int lx = l & 7;
#pragma unroll
    for (int c = 0; c < 8; c++) {
        float4 q = smv[cb + (c ^ lx)];
        f[4 * c] = q.x; f[4 * c + 1] = q.y; f[4 * c + 2] = q.z; f[4 * c + 3] = q.w;
    }
    // H32 over j (e-bits 0..4)
#pragma unroll
    for (int i = 0; i < 16; i++) z[i] = pack2(f[i] + f[i + 16], f[i] - f[i + 16]);
    h16_packed(z);
#pragma unroll
    for (int i = 0; i < 16; i++) unpack2(z[i], f[i], f[i + 16]);

    // ==== X1: write back IN-PLACE to the same slots (own slots -> no CTA sync) ====
#pragma unroll
    for (int c = 0; c < 8; c++)
        smv[cb + (c ^ lx)] =
            make_float4(f[4 * c], f[4 * c + 1], f[4 * c + 2], f[4 * c + 3]);
    __syncwarp();   // X1->PhB dependency is warp-internal (both in [1024wp, +1024))

    // ==== Phase B: read e = l + 32r + 1024wp at sws(e) = 1024wp + 32r + (l^((r&7)<<2)) ====
    const int wb = wp << 10;
#pragma unroll
    for (int r = 0; r < 32; r++)
        f[r] = sm[wb + 32 * r + (l ^ ((r & 7) << 2))];
    // H32 over r (e-bits 5..9)
#pragma unroll
    for (int i = 0; i < 16; i++) z[i] = pack2(f[i] + f[i + 16], f[i] - f[i + 16]);
    h16_packed(z);
#pragma unroll
    for (int i = 0; i < 16; i++) unpack2(z[i], f[i], f[i + 16]);

    // ==== X2: write back IN-PLACE (own slots -> no sync needed before this) ====
#pragma unroll
    for (int r = 0; r < 32; r++)
        sm[wb + 32 * r + (l ^ ((r & 7) << 2))] = f[r];
    __syncthreads();   // PhC reads across warps

    // ==== Phase C: thread owns e = s + 4l + 128wp + 1024w (s=0..3, w=0..7) ====
    // chunk = (l + 32wp + 256w) ^ m3, m3 = (l>>3)|((wp&1)<<2) -> 8x LDS.128 conflict-free
    {
        const int m3   = (l >> 3) | ((wp & 1) << 2);
        const int rb   = l + 32 * wp;
        ull za[8], zb[8];
#pragma unroll
        for (int w = 0; w < 8; w++) {
            float4 q = smv[(rb + 256 * w) ^ m3];
            za[w] = pack2(q.x, q.y);
            zb[w] = pack2(q.z, q.w);
        }
        // H8 over w (e-bits 10..12)
#pragma unroll
        for (int m = 4; m >= 1; m >>= 1) {
#pragma unroll
            for (int j = 0; j < 8; j++) {
                if ((j & m) == 0) {
                    ull a = za[j], b = za[j | m];
                    za[j]     = f2add(a, b);
                    za[j | m] = f2sub(a, b);
                    ull c = zb[j], d = zb[j | m];
                    zb[j]     = f2add(c, d);
                    zb[j | m] = f2sub(c, d);
                }
            }
        }
        const float SCALE = 0.011048543456039806f;  // 1/sqrt(8192)
        const ull SC2 = pack2(SCALE, SCALE);
        float4* orow = reinterpret_cast<float4*>(out + (long)row * DDIM);
#pragma unroll
        for (int w = 0; w < 8; w++) {
            float x0, x1, x2, x3;
            unpack2(f2mul(za[w], SC2), x0, x1);
            unpack2(f2mul(zb[w], SC2), x2, x3);
            orow[rb + 256 * w] = make_float4(x0, x1, x2, x3);
        }
    }
}

extern "C" void kernel_launch(void* const* d_in, const int* in_sizes, int n_in,
                              void* d_out, int out_size)
{
    const float* u   = (const float*)d_in[0];
    const int*   idx = (const int*)d_in[1];
    float*       out = (float*)d_out;
    fwht_kernel<<<NROWS, NTHREADS>>>(u, idx, out);
}

// round 6
// speedup vs baseline: 2.1278x; 1.0321x over previous
#include <cuda_runtime.h>

#define NROWS 8192
#define DDIM  8192
#define KIN   1024
#define NTHREADS 256
#define GRID   2048
#define RPB    (NROWS / GRID)   // 4 rows per block

typedef unsigned long long ull;

// ---- packed f32x2 helpers (Blackwell sm_103a) ----
__device__ __forceinline__ ull pack2(float lo, float hi) {
    ull r; asm("mov.b64 %0, {%1, %2};" : "=l"(r) : "f"(lo), "f"(hi)); return r;
}
__device__ __forceinline__ void unpack2(ull v, float& lo, float& hi) {
    asm("mov.b64 {%0, %1}, %2;" : "=f"(lo), "=f"(hi) : "l"(v));
}
__device__ __forceinline__ ull f2add(ull a, ull b) {
    ull r; asm("add.rn.f32x2 %0, %1, %2;" : "=l"(r) : "l"(a), "l"(b)); return r;
}
// a - b == fma(b, -1, a)
__device__ __forceinline__ ull f2sub(ull a, ull b) {
    const ull NEG1 = 0xBF800000BF800000ULL;
    ull r; asm("fma.rn.f32x2 %0, %1, %2, %3;" : "=l"(r) : "l"(b), "l"(NEG1), "l"(a)); return r;
}
__device__ __forceinline__ ull f2mul(ull a, ull b) {
    ull r; asm("mul.rn.f32x2 %0, %1, %2;" : "=l"(r) : "l"(a), "l"(b)); return r;
}

// Single storage layout for all phases: slot(e) = e ^ (((e>>5)&7)<<2)
__device__ __forceinline__ int sws(int e) {
    return e ^ (((e >> 5) & 7) << 2);
}

// Packed Hadamard over 16 x f32x2 (4 bits; 5th bit folded at pack time)
__device__ __forceinline__ void h16_packed(ull* y) {
#pragma unroll
    for (int m = 8; m >= 1; m >>= 1) {
#pragma unroll
        for (int j = 0; j < 16; j++) {
            if ((j & m) == 0) {
                ull a = y[j], b = y[j | m];
                y[j]     = f2add(a, b);
                y[j | m] = f2sub(a, b);
            }
        }
    }
}

__global__ void __launch_bounds__(NTHREADS, 4) fwht_kernel(
    const float* __restrict__ u, const int* __restrict__ idx, float* __restrict__ out)
{
    __shared__ float sm[DDIM];   // 32 KB, single in-place buffer
    float4* smv = reinterpret_cast<float4*>(sm);

    const int t   = threadIdx.x;
    const int l   = t & 31;   // lane
    const int wp  = t >> 5;   // warp (0..7)

    // ---- row-invariant setup: idx (same for every row) ----
    const int4 iv = reinterpret_cast<const int4*>(idx)[t];
    const int  k0 = 4 * t;
    const int  prev0 = (t == 0) ? -1 : idx[k0 - 1];
    int id[4] = {iv.x, iv.y, iv.z, iv.w};

    // PhA addressing constants
    const int cb = ((l + 32 * wp) << 3);
    const int lx = l & 7;
    const int wb = wp << 10;
    // PhC addressing constants
    const int m3 = (l >> 3) | ((wp & 1) << 2);
    const int rb = l + 32 * wp;

    int row = blockIdx.x;
    float4 uv = reinterpret_cast<const float4*>(u + (long)row * KIN)[t];

#pragma unroll
    for (int it = 0; it < RPB; it++) {
        const float* urow = u + (long)row * KIN;

        // ---- zero smem (32KB, STS.128, conflict-free) ----
        const float4 z4 = make_float4(0.f, 0.f, 0.f, 0.f);
#pragma unroll
        for (int i = 0; i < DDIM / 4 / NTHREADS; i++) smv[t + NTHREADS * i] = z4;
        __syncthreads();

        // ---- scatter: idx SORTED -> run-leader plain stores ----
        {
            float uu[4] = {uv.x, uv.y, uv.z, uv.w};
            int prev = prev0;
#pragma unroll
            for (int p = 0; p < 4; p++) {
                if (id[p] != prev) {
                    float val = uu[p];
                    int q = p + 1;
                    while (q < 4 && id[q] == id[p]) { val += uu[q]; q++; }
                    if (q == 4) {
                        int j = k0 + 4;   // run spills into next quad (rare)
                        while (j < KIN && idx[j] == id[p]) { val += urow[j]; j++; }
                    }
                    sm[sws(id[p])] = val;
                }
                prev = id[p];
            }
        }
        __syncthreads();

        // ---- prefetch next row's u (hidden under the FWHT below) ----
        if (it + 1 < RPB)
            uv = reinterpret_cast<const float4*>(u + (long)(row + GRID) * KIN)[t];

        float f[32];
        ull   z[16];

        // ==== Phase A: thread owns e = j + 32l + 1024wp ; 8x LDS.128 conflict-free ====
#pragma unroll
        for (int c = 0; c < 8; c++) {
            float4 q = smv[cb + (c ^ lx)];
            f[4 * c] = q.x; f[4 * c + 1] = q.y; f[4 * c + 2] = q.z; f[4 * c + 3] = q.w;
        }
        // H32 over e-bits 0..4
#pragma unroll
        for (int i = 0; i < 16; i++) z[i] = pack2(f[i] + f[i + 16], f[i] - f[i + 16]);
        h16_packed(z);
#pragma unroll
        for (int i = 0; i < 16; i++) unpack2(z[i], f[i], f[i + 16]);

        // ==== X1: write back IN-PLACE (own slots) ====
#pragma unroll
        for (int c = 0; c < 8; c++)
            smv[cb + (c ^ lx)] =
                make_float4(f[4 * c], f[4 * c + 1], f[4 * c + 2], f[4 * c + 3]);
        __syncwarp();   // X1->PhB dependency is warp-internal

        // ==== Phase B: read e = l + 32r + 1024wp at wb + 32r + (l^((r&7)<<2)) ====
#pragma unroll
        for (int r = 0; r < 32; r++)
            f[r] = sm[wb + 32 * r + (l ^ ((r & 7) << 2))];
        // H32 over e-bits 5..9
#pragma unroll
        for (int i = 0; i < 16; i++) z[i] = pack2(f[i] + f[i + 16], f[i] - f[i + 16]);
        h16_packed(z);
#pragma unroll
        for (int i = 0; i < 16; i++) unpack2(z[i], f[i], f[i + 16]);

        // ==== X2: write back IN-PLACE (own slots) ====
#pragma unroll
        for (int r = 0; r < 32; r++)
            sm[wb + 32 * r + (l ^ ((r & 7) << 2))] = f[r];
        __syncthreads();   // PhC reads across warps

        // ==== Phase C: thread owns e = s + 4l + 128wp + 1024w ; 8x LDS.128 ====
        ull za[8], zb[8];
#pragma unroll
        for (int w = 0; w < 8; w++) {
            float4 q = smv[(rb + 256 * w) ^ m3];
            za[w] = pack2(q.x, q.y);
            zb[w] = pack2(q.z, q.w);
        }
        __syncthreads();   // all PhC reads done before next row's zero overwrites

        // H8 over e-bits 10..12
#pragma unroll
        for (int m = 4; m >= 1; m >>= 1) {
#pragma unroll
            for (int j = 0; j < 8; j++) {
                if ((j & m) == 0) {
                    ull a = za[j], b = za[j | m];
                    za[j]     = f2add(a, b);
                    za[j | m] = f2sub(a, b);
                    ull c = zb[j], d = zb[j | m];
                    zb[j]     = f2add(c, d);
                    zb[j | m] = f2sub(c, d);
                }
            }
        }
        const float SCALE = 0.011048543456039806f;  // 1/sqrt(8192)
        const ull SC2 = pack2(SCALE, SCALE);
        float4* orow = reinterpret_cast<float4*>(out + (long)row * DDIM);
#pragma unroll
        for (int w = 0; w < 8; w++) {
            float x0, x1, x2, x3;
            unpack2(f2mul(za[w], SC2), x0, x1);
            unpack2(f2mul(zb[w], SC2), x2, x3);
            orow[rb + 256 * w] = make_float4(x0, x1, x2, x3);
        }

        row += GRID;
    }
}

extern "C" void kernel_launch(void* const* d_in, const int* in_sizes, int n_in,
                              void* d_out, int out_size)
{
    const float* u   = (const float*)d_in[0];
    const int*   idx = (const int*)d_in[1];
    float*       out = (float*)d_out;
    fwht_kernel<<<GRID, NTHREADS>>>(u, idx, out);
}

// round 8
// speedup vs baseline: 2.2999x; 1.0809x over previous
#include <cuda_runtime.h>

#define NROWS 8192
#define DDIM  8192
#define KIN   1024
#define NT    64

typedef unsigned long long ull;

// ---- packed f32x2 helpers (Blackwell sm_103a) ----
__device__ __forceinline__ ull pack2(float lo, float hi) {
    ull r; asm("mov.b64 %0, {%1, %2};" : "=l"(r) : "f"(lo), "f"(hi)); return r;
}
__device__ __forceinline__ void unpack2(ull v, float& lo, float& hi) {
    asm("mov.b64 {%0, %1}, %2;" : "=f"(lo), "=f"(hi) : "l"(v));
}
__device__ __forceinline__ ull f2add(ull a, ull b) {
    ull r; asm("add.rn.f32x2 %0, %1, %2;" : "=l"(r) : "l"(a), "l"(b)); return r;
}
// a - b == fma(b, -1, a)
__device__ __forceinline__ ull f2sub(ull a, ull b) {
    const ull NEG1 = 0xBF800000BF800000ULL;
    ull r; asm("fma.rn.f32x2 %0, %1, %2, %3;" : "=l"(r) : "l"(b), "l"(NEG1), "l"(a)); return r;
}
__device__ __forceinline__ ull f2mul(ull a, ull b) {
    ull r; asm("mul.rn.f32x2 %0, %1, %2;" : "=l"(r) : "l"(a), "l"(b)); return r;
}

// Storage swizzle: slot(e) = e ^ (((e>>7)&31)<<2)  (perturbs bits 2..6 only)
__device__ __forceinline__ int slot(int e) {
    return e ^ (((e >> 7) & 31) << 2);
}

__global__ void __launch_bounds__(NT, 6) fwht_kernel(
    const float* __restrict__ u, const int* __restrict__ idx, float* __restrict__ out)
{
    __shared__ float sm[DDIM];   // 32 KB, single in-place buffer
    float4* smv = reinterpret_cast<float4*>(sm);

    const int t   = threadIdx.x;       // 0..63
    const int row = blockIdx.x;
    const float* urow = u + (long)row * KIN;

    // ---- early global loads (16 keys + 16 values per thread) ----
    int4   iv[4];
    float4 uv[4];
    const int4*   idx4 = reinterpret_cast<const int4*>(idx);
    const float4* u4   = reinterpret_cast<const float4*>(urow);
#pragma unroll
    for (int i = 0; i < 4; i++) { iv[i] = idx4[4 * t + i]; uv[i] = u4[4 * t + i]; }
    int prev = (t == 0) ? -1 : idx[16 * t - 1];

    // ---- zero smem (32KB, STS.128, conflict-free), overlaps LDG latency ----
    const float4 z4 = make_float4(0.f, 0.f, 0.f, 0.f);
#pragma unroll
    for (int i = 0; i < DDIM / 4 / NT; i++) smv[t + NT * i] = z4;
    __syncthreads();

    // ---- scatter: idx SORTED -> run-leader plain stores (no atomics) ----
    {
        int   id[16]; float uu[16];
#pragma unroll
        for (int i = 0; i < 4; i++) {
            id[4*i] = iv[i].x; id[4*i+1] = iv[i].y; id[4*i+2] = iv[i].z; id[4*i+3] = iv[i].w;
            uu[4*i] = uv[i].x; uu[4*i+1] = uv[i].y; uu[4*i+2] = uv[i].z; uu[4*i+3] = uv[i].w;
        }
#pragma unroll
        for (int p = 0; p < 16; p++) {
            if (id[p] != prev) {
                float val = uu[p];
                int q = p + 1;
                while (q < 16 && id[q] == id[p]) { val += uu[q]; q++; }
                if (q == 16) {
                    int j = 16 * t + 16;   // run spills past this thread's keys (rare)
                    while (j < KIN && idx[j] == id[p]) { val += urow[j]; j++; }
                }
                sm[slot(id[p])] = val;
            }
            prev = id[p];
        }
    }
    __syncthreads();

    // ==== Phase 1: thread owns e in [128t, 128t+128); bits 0..6 in registers ====
    // e-quad c stored at slot-quad 32t + (c ^ (t&31))  -> 32x LDS.128 conflict-free
    {
        ull y[64];
        const int tm = t & 31;
        const int qb = t << 5;
#pragma unroll
        for (int c = 0; c < 32; c++) {
            float4 q = smv[qb + (c ^ tm)];
            y[2 * c]     = pack2(q.x + q.y, q.x - q.y);   // fold bit 0
            y[2 * c + 1] = pack2(q.z + q.w, q.z - q.w);
        }
        // bits 1..6: 6 packed stages over pair-index p = 0..63
#pragma unroll
        for (int m = 32; m >= 1; m >>= 1) {
#pragma unroll
            for (int j = 0; j < 64; j++) {
                if (!(j & m)) {
                    ull a = y[j], b = y[j | m];
                    y[j]     = f2add(a, b);
                    y[j | m] = f2sub(a, b);
                }
            }
        }
        // write back IN-PLACE (thread-exclusive slots, same addresses)
#pragma unroll
        for (int c = 0; c < 32; c++) {
            float a0, a1, b0, b1;
            unpack2(y[2 * c], a0, a1);
            unpack2(y[2 * c + 1], b0, b1);
            smv[qb + (c ^ tm)] = make_float4(a0, a1, b0, b1);
        }
    }
    __syncthreads();   // P2 reads cross-thread

    // ==== Phase 2: bits 7..12. Each thread handles TWO tau columns: t and t+64 ====
    const float SCALE = 0.011048543456039806f;  // 1/sqrt(8192)
    const ull SC2 = pack2(SCALE, SCALE);
    float* orow = out + (long)row * DDIM;
#pragma unroll 1
    for (int pass = 0; pass < 2; pass++) {
        const int tau = t + 64 * pass;
        ull z[32];
        // read e = tau + 128m at slot = 128m + (tau ^ ((m&31)<<2)); fold bit 7
#pragma unroll
        for (int h = 0; h < 32; h++) {
            const int m0 = 2 * h, m1 = 2 * h + 1;
            float a = sm[128 * m0 + (tau ^ ((m0 & 31) << 2))];
            float b = sm[128 * m1 + (tau ^ ((m1 & 31) << 2))];
            z[h] = pack2(a + b, a - b);
        }
        // bits 8..12: 5 packed stages over h = 0..31
#pragma unroll
        for (int m = 16; m >= 1; m >>= 1) {
#pragma unroll
            for (int j = 0; j < 32; j++) {
                if (!(j & m)) {
                    ull a = z[j], b = z[j | m];
                    z[j]     = f2add(a, b);
                    z[j | m] = f2sub(a, b);
                }
            }
        }
        // scale + store: lo -> orow[tau + 256h], hi -> orow[tau + 256h + 128]
#pragma unroll
        for (int h = 0; h < 32; h++) {
            float lo, hi;
            unpack2(f2mul(z[h], SC2), lo, hi);
            orow[tau + 256 * h]       = lo;
            orow[tau + 256 * h + 128] = hi;
        }
    }
}

extern "C" void kernel_launch(void* const* d_in, const int* in_sizes, int n_in,
                              void* d_out, int out_size)
{
    const float* u   = (const float*)d_in[0];
    const int*   idx = (const int*)d_in[1];
    float*       out = (float*)d_out;
    fwht_kernel<<<NROWS, NT>>>(u, idx, out);
}